// round 16
// baseline (speedup 1.0000x reference)
#include <cuda_runtime.h>
#include <cuda_bf16.h>
#include <cstdint>
#include <cstddef>

#define LL 32
#define HH 128
#define KD 130
#define KPE 136
#define SPB 2
#define NBLK 256
#define NTHR 128
#define NCELL 1024
#define EPSF 1e-8f
#define W_BYTES  (HH * KPE * 2u)   // 34816
#define AUX_BYTES 2048u
#define TX_BYTES (W_BYTES + AUX_BYTES)

#define OFF_W    0u        // 2 x 34816
#define OFF_AUX  69632u    // 2 x 2048
#define OFF_BT   73728u    // 2 x 2176 (Bt[8][136] bf16)
#define OFF_HV   78080u    // 16384 (u32 bf16x2 [32][128])
#define OFF_RED  94464u    // float2[2][4]
#define OFF_SB   94528u    // 256
#define OFF_MB   94784u    // 16
#define SMEM_SZ  94816u

typedef unsigned long long ull;

__device__ unsigned short g_Wb[(size_t)NCELL * HH * KPE];  // bf16 W[:,2:130], rows padded to 136
__device__ float g_aux[(size_t)NCELL * HH * 4];            // [cell][n][{w0,w1,b,wf}]
__device__ float2 g_pre[NBLK][NCELL];

__device__ __forceinline__ uint32_t s2u(const void* p) {
    return (uint32_t)__cvta_generic_to_shared(p);
}
__device__ __forceinline__ void mbar_init(uint32_t a, uint32_t c) {
    asm volatile("mbarrier.init.shared::cta.b64 [%0], %1;" :: "r"(a), "r"(c) : "memory");
}
__device__ __forceinline__ void mbar_expect(uint32_t a, uint32_t tx) {
    asm volatile("mbarrier.arrive.expect_tx.shared::cta.b64 _, [%0], %1;" :: "r"(a), "r"(tx) : "memory");
}
__device__ __forceinline__ void tma1d(uint32_t dst, const void* src, uint32_t bytes, uint32_t mbar) {
    asm volatile("cp.async.bulk.shared::cluster.global.mbarrier::complete_tx::bytes [%0], [%1], %2, [%3];"
                 :: "r"(dst), "l"(src), "r"(bytes), "r"(mbar) : "memory");
}
__device__ __forceinline__ void mbar_wait(uint32_t a, uint32_t ph) {
    uint32_t done = 0;
    while (!done) {
        asm volatile("{\n\t.reg .pred p;\n\t"
                     "mbarrier.try_wait.parity.acquire.cta.shared::cta.b64 p, [%1], %2;\n\t"
                     "selp.b32 %0, 1, 0, p;\n\t}"
                     : "=r"(done) : "r"(a), "r"(ph) : "memory");
    }
}
__device__ __forceinline__ float tanh_fast(float x) {
    float y; asm("tanh.approx.f32 %0, %1;" : "=f"(y) : "f"(x)); return y;
}
__device__ __forceinline__ float bflo(uint32_t u) { return __uint_as_float(u << 16); }
__device__ __forceinline__ float bfhi(uint32_t u) { return __uint_as_float(u & 0xffff0000u); }
__device__ __forceinline__ uint32_t packbf2(float lo, float hi) {
    uint32_t r; asm("cvt.rn.bf16x2.f32 %0, %2, %1;" : "=r"(r) : "f"(lo), "f"(hi)); return r;
}
__device__ __forceinline__ unsigned short bf16b(float x) {
    unsigned short u; asm("cvt.rn.bf16.f32 %0, %1;" : "=h"(u) : "f"(x)); return u;
}
__device__ __forceinline__ void ldsm4(uint32_t& r0, uint32_t& r1, uint32_t& r2, uint32_t& r3, uint32_t addr) {
    asm volatile("ldmatrix.sync.aligned.m8n8.x4.shared.b16 {%0,%1,%2,%3}, [%4];"
                 : "=r"(r0), "=r"(r1), "=r"(r2), "=r"(r3) : "r"(addr));
}
__device__ __forceinline__ void mma16816(float* c, const uint32_t* a, uint32_t b0, uint32_t b1) {
    asm volatile("mma.sync.aligned.m16n8k16.row.col.f32.bf16.bf16.f32 "
                 "{%0,%1,%2,%3}, {%4,%5,%6,%7}, {%8,%9}, {%0,%1,%2,%3};"
                 : "+f"(c[0]), "+f"(c[1]), "+f"(c[2]), "+f"(c[3])
                 : "r"(a[0]), "r"(a[1]), "r"(a[2]), "r"(a[3]), "r"(b0), "r"(b1));
}

// ---- prep: W[:,2:130] -> bf16 padded rows; aux pack [n][{w0,w1,b,wf}] ----
__global__ void prep_kernel(const float* __restrict__ gW, const float* __restrict__ gB,
                            const float* __restrict__ gWf) {
    const int c = blockIdx.x;
    const float* src = gW + (size_t)c * (HH * KD);
    unsigned short* dst = g_Wb + (size_t)c * (HH * KPE);
    for (int t = threadIdx.x; t < HH * KPE; t += blockDim.x) {
        const int row = t / KPE, col = t - row * KPE;
        __nv_bfloat16 b = __float2bfloat16((col < HH) ? src[row * KD + 2 + col] : 0.f);
        dst[t] = *reinterpret_cast<unsigned short*>(&b);
    }
    float* da = g_aux + (size_t)c * HH * 4;
    for (int t = threadIdx.x; t < HH; t += blockDim.x) {
        da[t * 4 + 0] = src[t * KD + 0];
        da[t * 4 + 1] = src[t * KD + 1];
        da[t * 4 + 2] = gB[c * HH + t];
        da[t * 4 + 3] = gWf[c * HH + t];
    }
}

// ---- main: mma.sync matvec, preloaded frags + split chains ----
__global__ void __launch_bounds__(NTHR, 2)
rnn2d_kernel(const float* __restrict__ gS, const float* __restrict__ gBf,
             float* __restrict__ out)
{
    extern __shared__ unsigned char sb[];
    const uint32_t sbu = s2u(sb);
    const int tid = threadIdx.x, blk = blockIdx.x;
    const int lid = tid & 31, wid = tid >> 5;
    const int g = lid >> 2, tr = lid & 3;
    const int wb = wid * 32;

    uint32_t* HV = (uint32_t*)(sb + OFF_HV);
    float2*  RED = (float2*)(sb + OFF_RED);
    uint32_t* SB = (uint32_t*)(sb + OFF_SB);

    // ---- init ----
    const float* gs = gS + (size_t)blk * SPB * NCELL;
    if (tid < SPB * LL) {
        const int sm = tid >> 5, row = tid & 31;
        const float* rp = gs + sm * NCELL + row * LL;
        uint32_t bits = 0;
        #pragma unroll
        for (int jj = 0; jj < LL; ++jj) bits |= (rp[jj] > 0.5f ? 1u : 0u) << jj;
        SB[sm * 32 + row] = bits;
    }
    for (int t = tid; t < 4096; t += NTHR) HV[t] = 0u;
    for (int t = tid; t < 1088; t += NTHR) ((uint32_t*)(sb + OFF_BT))[t] = 0u;

    const uint32_t mb0 = sbu + OFF_MB, mb1 = sbu + OFF_MB + 8;
    if (tid == 0) {
        mbar_init(mb0, 1);
        mbar_init(mb1, 1);
        asm volatile("fence.mbarrier_init.release.cluster;" ::: "memory");
        mbar_expect(mb0, TX_BYTES);
        tma1d(sbu + OFF_W,   g_Wb,  W_BYTES,   mb0);
        tma1d(sbu + OFF_AUX, g_aux, AUX_BYTES, mb0);
    }
    __syncthreads();

    // ldmatrix lane geometry
    const int mtx = lid >> 3, rowin = lid & 7;
    const int mrow = ((mtx & 1) << 3) + rowin;
    const int kof = (mtx >> 1) << 3;

    for (int c = 0; c < NCELL; ++c) {
        const int buf = c & 1;
        const int r = c >> 5, j = c & 31;
        const int col = (r & 1) ? (LL - 1 - j) : j;

        // off-path: previous cell's head sum -> g_pre (tid 32)
        if (tid == 32 && c > 0) {
            const int pc = c - 1, pr = pc >> 5, pj = pc & 31;
            const int pcol = (pr & 1) ? (LL - 1 - pj) : pj;
            const float2 q0 = RED[(pc & 1) * 4 + 0], q1 = RED[(pc & 1) * 4 + 1];
            const float2 q2 = RED[(pc & 1) * 4 + 2], q3 = RED[(pc & 1) * 4 + 3];
            g_pre[blk][(pr << 5) + pcol] =
                make_float2(q0.x + q1.x + q2.x + q3.x, q0.y + q1.y + q2.y + q3.y);
        }
        if (tid == 0 && c + 1 < NCELL) {
            const int cn = c + 1, rn = cn >> 5, jn = cn & 31;
            const int coln = (rn & 1) ? (LL - 1 - jn) : jn;
            const int celln = (rn << 5) + coln;
            const uint32_t mb = buf ? mb0 : mb1;
            mbar_expect(mb, TX_BYTES);
            tma1d(sbu + OFF_W + (buf ^ 1) * W_BYTES,
                  g_Wb + (size_t)celln * HH * KPE, W_BYTES, mb);
            tma1d(sbu + OFF_AUX + (buf ^ 1) * AUX_BYTES,
                  g_aux + (size_t)celln * HH * 4, AUX_BYTES, mb);
        }
        mbar_wait(buf ? mb1 : mb0, (c >> 1) & 1);

        // ---- preload ALL fragments (16 ldsm4 + 16 LDS.32), then 4 MMA chains ----
        const uint32_t wbase = sbu + OFF_W + buf * W_BYTES;
        const uint32_t a0addr = wbase + (uint32_t)(wb + mrow) * 272u + (uint32_t)kof * 2u;
        const unsigned char* btp = sb + OFF_BT + buf * 2176 + g * 272 + tr * 4;

        uint32_t af0[8][4], af1[8][4], bfr[8][2];
        #pragma unroll
        for (int kt = 0; kt < 8; ++kt) {
            ldsm4(af0[kt][0], af0[kt][1], af0[kt][2], af0[kt][3], a0addr + kt * 32u);
            ldsm4(af1[kt][0], af1[kt][1], af1[kt][2], af1[kt][3], a0addr + kt * 32u + 16u * 272u);
        }
        #pragma unroll
        for (int kt = 0; kt < 8; ++kt) {
            bfr[kt][0] = *(const uint32_t*)(btp + kt * 32);
            bfr[kt][1] = *(const uint32_t*)(btp + kt * 32 + 16);
        }

        float c0a[4] = {0.f, 0.f, 0.f, 0.f}, c0b[4] = {0.f, 0.f, 0.f, 0.f};
        float c1a[4] = {0.f, 0.f, 0.f, 0.f}, c1b[4] = {0.f, 0.f, 0.f, 0.f};
        #pragma unroll
        for (int kt = 0; kt < 4; ++kt) {
            mma16816(c0a, af0[kt],     bfr[kt][0],     bfr[kt][1]);
            mma16816(c0b, af0[kt + 4], bfr[kt + 4][0], bfr[kt + 4][1]);
            mma16816(c1a, af1[kt],     bfr[kt][0],     bfr[kt][1]);
            mma16816(c1b, af1[kt + 4], bfr[kt + 4][0], bfr[kt + 4][1]);
        }
        float c0[4], c1[4];
        #pragma unroll
        for (int i = 0; i < 4; ++i) { c0[i] = c0a[i] + c0b[i]; c1[i] = c1a[i] + c1b[i]; }

        // ---- epilogue ----
        const int colprev = (r & 1) ? (col + 1) : (col - 1);
        const float xh0 = (j == 0) ? 0.f : (float)((SB[r] >> colprev) & 1u);
        const float xv0 = (r == 0) ? 0.f : (float)((SB[r - 1] >> col) & 1u);
        const float xh1 = (j == 0) ? 0.f : (float)((SB[32 + r] >> colprev) & 1u);
        const float xv1 = (r == 0) ? 0.f : (float)((SB[32 + r - 1] >> col) & 1u);
        const float e0 = xh0 + xv0, e1 = xh1 + xv1;

        const float4* AUX = (const float4*)(sb + OFF_AUX + buf * AUX_BYTES);
        const int n0 = wb + g, n1 = wb + g + 8, n2 = wb + g + 16, n3 = wb + g + 24;
        const float4 x0 = AUX[n0], x1 = AUX[n1], x2 = AUX[n2], x3 = AUX[n3];

        const float h00 = tanh_fast(c0[0] + 2.f * x0.z + x0.x * e0 + x0.y * (2.f - e0));
        const float h01 = tanh_fast(c0[1] + 2.f * x0.z + x0.x * e1 + x0.y * (2.f - e1));
        const float h10 = tanh_fast(c0[2] + 2.f * x1.z + x1.x * e0 + x1.y * (2.f - e0));
        const float h11 = tanh_fast(c0[3] + 2.f * x1.z + x1.x * e1 + x1.y * (2.f - e1));
        const float h20 = tanh_fast(c1[0] + 2.f * x2.z + x2.x * e0 + x2.y * (2.f - e0));
        const float h21 = tanh_fast(c1[1] + 2.f * x2.z + x2.x * e1 + x2.y * (2.f - e1));
        const float h30 = tanh_fast(c1[2] + 2.f * x3.z + x3.x * e0 + x3.y * (2.f - e0));
        const float h31 = tanh_fast(c1[3] + 2.f * x3.z + x3.x * e1 + x3.y * (2.f - e1));

        float p0 = x0.w * h00 + x1.w * h10 + x2.w * h20 + x3.w * h30;
        float p1 = x0.w * h01 + x1.w * h11 + x2.w * h21 + x3.w * h31;
        if (tr != 0) { p0 = 0.f; p1 = 0.f; }
        #pragma unroll
        for (int o = 4; o <= 16; o <<= 1) {
            p0 += __shfl_xor_sync(0xffffffffu, p0, o);
            p1 += __shfl_xor_sync(0xffffffffu, p1, o);
        }
        if (lid == 0) RED[(c & 1) * 4 + wid] = make_float2(p0, p1);

        if (tr == 0) {
            HV[col * 128 + n0] = packbf2(h00, h01);
            HV[col * 128 + n1] = packbf2(h10, h11);
            HV[col * 128 + n2] = packbf2(h20, h21);
            HV[col * 128 + n3] = packbf2(h30, h31);
            if (c + 1 < NCELL) {
                const int cn = c + 1, rn = cn >> 5, jn = cn & 31;
                const int coln = (rn & 1) ? (LL - 1 - jn) : jn;
                float v00 = h00, v01 = h01, v10 = h10, v11 = h11;
                float v20 = h20, v21 = h21, v30 = h30, v31 = h31;
                if (jn != 0) {
                    const uint32_t t0 = HV[coln * 128 + n0];
                    const uint32_t t1 = HV[coln * 128 + n1];
                    const uint32_t t2 = HV[coln * 128 + n2];
                    const uint32_t t3 = HV[coln * 128 + n3];
                    v00 += bflo(t0); v01 += bfhi(t0);
                    v10 += bflo(t1); v11 += bfhi(t1);
                    v20 += bflo(t2); v21 += bfhi(t2);
                    v30 += bflo(t3); v31 += bfhi(t3);
                }
                unsigned short* bt0 = (unsigned short*)(sb + OFF_BT + (buf ^ 1) * 2176);
                unsigned short* bt1 = bt0 + 136;
                bt0[n0] = bf16b(v00); bt1[n0] = bf16b(v01);
                bt0[n1] = bf16b(v10); bt1[n1] = bf16b(v11);
                bt0[n2] = bf16b(v20); bt1[n2] = bf16b(v21);
                bt0[n3] = bf16b(v30); bt1[n3] = bf16b(v31);
            }
        }
        __syncthreads();
    }

    // last cell's pre
    if (tid == 32) {
        const int pc = NCELL - 1, pr = pc >> 5, pj = pc & 31;
        const int pcol = (pr & 1) ? (LL - 1 - pj) : pj;
        const float2 q0 = RED[(pc & 1) * 4 + 0], q1 = RED[(pc & 1) * 4 + 1];
        const float2 q2 = RED[(pc & 1) * 4 + 2], q3 = RED[(pc & 1) * 4 + 3];
        g_pre[blk][(pr << 5) + pcol] =
            make_float2(q0.x + q1.x + q2.x + q3.x, q0.y + q1.y + q2.y + q3.y);
    }
    __syncthreads();

    // ---- bulk log-prob ----
    float lp0 = 0.f, lp1 = 0.f;
    for (int c = tid; c < NCELL; c += NTHR) {
        const float bfv = __ldg(gBf + c);
        const float2 pr = g_pre[blk][c];
        const int row = c >> 5, bit = c & 31;
        float z, xh, m;
        z = pr.x + bfv; xh = 1.f / (1.f + __expf(-z));
        m = (float)((SB[row] >> bit) & 1u);
        lp0 += m * __logf(xh + EPSF) + (1.f - m) * __logf(1.f - xh + EPSF);
        z = pr.y + bfv; xh = 1.f / (1.f + __expf(-z));
        m = (float)((SB[32 + row] >> bit) & 1u);
        lp1 += m * __logf(xh + EPSF) + (1.f - m) * __logf(1.f - xh + EPSF);
    }
    #pragma unroll
    for (int o = 16; o; o >>= 1) {
        lp0 += __shfl_xor_sync(0xffffffffu, lp0, o);
        lp1 += __shfl_xor_sync(0xffffffffu, lp1, o);
    }
    if (lid == 0) RED[wid] = make_float2(lp0, lp1);
    __syncthreads();
    if (tid < SPB) {
        float acc = 0.f;
        #pragma unroll
        for (int w = 0; w < 4; ++w) acc += ((const float*)&RED[w])[tid];
        out[blk * SPB + tid] = acc;
    }
}

extern "C" void kernel_launch(void* const* d_in, const int* in_sizes, int n_in,
                              void* d_out, int out_size) {
    const float* samples = (const float*)d_in[0];
    const float* W1      = (const float*)d_in[1];
    const float* b1      = (const float*)d_in[2];
    const float* Wf      = (const float*)d_in[3];
    const float* bf      = (const float*)d_in[4];
    float* out = (float*)d_out;

    prep_kernel<<<NCELL, 256>>>(W1, b1, Wf);

    cudaFuncSetAttribute(rnn2d_kernel, cudaFuncAttributeMaxDynamicSharedMemorySize, (int)SMEM_SZ);
    rnn2d_kernel<<<NBLK, NTHR, SMEM_SZ>>>(samples, bf, out);
}

// round 17
// speedup vs baseline: 1.2397x; 1.2397x over previous
#include <cuda_runtime.h>
#include <cuda_bf16.h>
#include <cstdint>
#include <cstddef>

#define LL 32
#define HH 128
#define KD 130
#define KPE 136
#define SPB 4
#define NBLK 128
#define NTHR 256
#define NCELL 1024
#define EPSF 1e-8f
#define W_BYTES  (HH * KPE * 2u)   // 34816
#define AUX_BYTES 2048u
#define TX_BYTES (W_BYTES + AUX_BYTES)

#define OFF_W    0u         // 2 x 34816
#define OFF_AUX  69632u     // 2 x 2048
#define OFF_BT   73728u     // 2 x 2176 (Bt[8][136] bf16, rows = N-cols/samples)
#define OFF_HV01 78080u     // 16384 u32 bf16x2 (samples 0,1)
#define OFF_HV23 94464u     // 16384 u32 bf16x2 (samples 2,3)
#define OFF_RED  110848u    // float2[2][8][2]
#define OFF_SB   111104u    // 512 (4 samples x 32 rows)
#define OFF_MB   111616u    // 16
#define SMEM_SZ  111648u

typedef unsigned long long ull;

__device__ unsigned short g_Wb[(size_t)NCELL * HH * KPE];  // bf16 W[:,2:130], rows padded to 136
__device__ float g_aux[(size_t)NCELL * HH * 4];            // [cell][n][{w0,w1,b,wf}]
__device__ float4 g_pre[NBLK][NCELL];

__device__ __forceinline__ uint32_t s2u(const void* p) {
    return (uint32_t)__cvta_generic_to_shared(p);
}
__device__ __forceinline__ void mbar_init(uint32_t a, uint32_t c) {
    asm volatile("mbarrier.init.shared::cta.b64 [%0], %1;" :: "r"(a), "r"(c) : "memory");
}
__device__ __forceinline__ void mbar_expect(uint32_t a, uint32_t tx) {
    asm volatile("mbarrier.arrive.expect_tx.shared::cta.b64 _, [%0], %1;" :: "r"(a), "r"(tx) : "memory");
}
__device__ __forceinline__ void tma1d(uint32_t dst, const void* src, uint32_t bytes, uint32_t mbar) {
    asm volatile("cp.async.bulk.shared::cluster.global.mbarrier::complete_tx::bytes [%0], [%1], %2, [%3];"
                 :: "r"(dst), "l"(src), "r"(bytes), "r"(mbar) : "memory");
}
__device__ __forceinline__ void mbar_wait(uint32_t a, uint32_t ph) {
    uint32_t done = 0;
    while (!done) {
        asm volatile("{\n\t.reg .pred p;\n\t"
                     "mbarrier.try_wait.parity.acquire.cta.shared::cta.b64 p, [%1], %2;\n\t"
                     "selp.b32 %0, 1, 0, p;\n\t}"
                     : "=r"(done) : "r"(a), "r"(ph) : "memory");
    }
}
__device__ __forceinline__ float tanh_fast(float x) {
    float y; asm("tanh.approx.f32 %0, %1;" : "=f"(y) : "f"(x)); return y;
}
__device__ __forceinline__ float bflo(uint32_t u) { return __uint_as_float(u << 16); }
__device__ __forceinline__ float bfhi(uint32_t u) { return __uint_as_float(u & 0xffff0000u); }
__device__ __forceinline__ uint32_t packbf2(float lo, float hi) {
    uint32_t r; asm("cvt.rn.bf16x2.f32 %0, %2, %1;" : "=r"(r) : "f"(lo), "f"(hi)); return r;
}
__device__ __forceinline__ unsigned short bf16b(float x) {
    unsigned short u; asm("cvt.rn.bf16.f32 %0, %1;" : "=h"(u) : "f"(x)); return u;
}
__device__ __forceinline__ void ldsm4(uint32_t& r0, uint32_t& r1, uint32_t& r2, uint32_t& r3, uint32_t addr) {
    asm volatile("ldmatrix.sync.aligned.m8n8.x4.shared.b16 {%0,%1,%2,%3}, [%4];"
                 : "=r"(r0), "=r"(r1), "=r"(r2), "=r"(r3) : "r"(addr));
}
__device__ __forceinline__ void mma16816(float* c, const uint32_t* a, uint32_t b0, uint32_t b1) {
    asm volatile("mma.sync.aligned.m16n8k16.row.col.f32.bf16.bf16.f32 "
                 "{%0,%1,%2,%3}, {%4,%5,%6,%7}, {%8,%9}, {%0,%1,%2,%3};"
                 : "+f"(c[0]), "+f"(c[1]), "+f"(c[2]), "+f"(c[3])
                 : "r"(a[0]), "r"(a[1]), "r"(a[2]), "r"(a[3]), "r"(b0), "r"(b1));
}

// ---- prep: W[:,2:130] -> bf16 padded rows; aux pack [n][{w0,w1,b,wf}] ----
__global__ void prep_kernel(const float* __restrict__ gW, const float* __restrict__ gB,
                            const float* __restrict__ gWf) {
    const int c = blockIdx.x;
    const float* src = gW + (size_t)c * (HH * KD);
    unsigned short* dst = g_Wb + (size_t)c * (HH * KPE);
    for (int t = threadIdx.x; t < HH * KPE; t += blockDim.x) {
        const int row = t / KPE, col = t - row * KPE;
        __nv_bfloat16 b = __float2bfloat16((col < HH) ? src[row * KD + 2 + col] : 0.f);
        dst[t] = *reinterpret_cast<unsigned short*>(&b);
    }
    float* da = g_aux + (size_t)c * HH * 4;
    for (int t = threadIdx.x; t < HH; t += blockDim.x) {
        da[t * 4 + 0] = src[t * KD + 0];
        da[t * 4 + 1] = src[t * KD + 1];
        da[t * 4 + 2] = gB[c * HH + t];
        da[t * 4 + 3] = gWf[c * HH + t];
    }
}

// ---- main: 8-warp CTA, warp = m16 tile, 4 samples in MMA N dim ----
__global__ void __launch_bounds__(NTHR, 1)
rnn2d_kernel(const float* __restrict__ gS, const float* __restrict__ gBf,
             float* __restrict__ out)
{
    extern __shared__ unsigned char sb[];
    const uint32_t sbu = s2u(sb);
    const int tid = threadIdx.x, blk = blockIdx.x;
    const int lid = tid & 31, wid = tid >> 5;
    const int g = lid >> 2, tr = lid & 3;

    uint32_t* HV01 = (uint32_t*)(sb + OFF_HV01);
    uint32_t* HV23 = (uint32_t*)(sb + OFF_HV23);
    float2*  RED = (float2*)(sb + OFF_RED);      // [cbuf][wid][tr<2]
    uint32_t* SB = (uint32_t*)(sb + OFF_SB);

    // ---- init ----
    const float* gs = gS + (size_t)blk * SPB * NCELL;
    if (tid < SPB * LL) {
        const int sm = tid >> 5, row = tid & 31;
        const float* rp = gs + sm * NCELL + row * LL;
        uint32_t bits = 0;
        #pragma unroll
        for (int jj = 0; jj < LL; ++jj) bits |= (rp[jj] > 0.5f ? 1u : 0u) << jj;
        SB[sm * 32 + row] = bits;
    }
    for (int t = tid; t < 4096; t += NTHR) { HV01[t] = 0u; HV23[t] = 0u; }
    for (int t = tid; t < 1088; t += NTHR) ((uint32_t*)(sb + OFF_BT))[t] = 0u;

    const uint32_t mb0 = sbu + OFF_MB, mb1 = sbu + OFF_MB + 8;
    if (tid == 0) {
        mbar_init(mb0, 1);
        mbar_init(mb1, 1);
        asm volatile("fence.mbarrier_init.release.cluster;" ::: "memory");
        mbar_expect(mb0, TX_BYTES);
        tma1d(sbu + OFF_W,   g_Wb,  W_BYTES,   mb0);
        tma1d(sbu + OFF_AUX, g_aux, AUX_BYTES, mb0);
    }
    __syncthreads();

    // ldmatrix lane geometry (one m16 tile per warp)
    const int mtx = lid >> 3, rowin = lid & 7;
    const int mrow = ((mtx & 1) << 3) + rowin;   // 0..15
    const int kof = (mtx >> 1) << 3;             // 0 or 8

    for (int c = 0; c < NCELL; ++c) {
        const int buf = c & 1;
        const int r = c >> 5, j = c & 31;
        const int col = (r & 1) ? (LL - 1 - j) : j;

        // off-path: previous cell's head sums -> g_pre (tid 32 = warp1 lane0)
        if (tid == 32 && c > 0) {
            const int pc = c - 1, pr = pc >> 5, pj = pc & 31;
            const int pcol = (pr & 1) ? (LL - 1 - pj) : pj;
            float s01x = 0.f, s01y = 0.f, s23x = 0.f, s23y = 0.f;
            #pragma unroll
            for (int w = 0; w < 8; ++w) {
                const float2 qa = RED[((pc & 1) * 8 + w) * 2 + 0];
                const float2 qb = RED[((pc & 1) * 8 + w) * 2 + 1];
                s01x += qa.x; s01y += qa.y; s23x += qb.x; s23y += qb.y;
            }
            g_pre[blk][(pr << 5) + pcol] = make_float4(s01x, s01y, s23x, s23y);
        }
        if (tid == 0 && c + 1 < NCELL) {
            const int cn = c + 1, rn = cn >> 5, jn = cn & 31;
            const int coln = (rn & 1) ? (LL - 1 - jn) : jn;
            const int celln = (rn << 5) + coln;
            const uint32_t mb = buf ? mb0 : mb1;
            mbar_expect(mb, TX_BYTES);
            tma1d(sbu + OFF_W + (buf ^ 1) * W_BYTES,
                  g_Wb + (size_t)celln * HH * KPE, W_BYTES, mb);
            tma1d(sbu + OFF_AUX + (buf ^ 1) * AUX_BYTES,
                  g_aux + (size_t)celln * HH * 4, AUX_BYTES, mb);
        }
        mbar_wait(buf ? mb1 : mb0, (c >> 1) & 1);

        // ---- matvec: warp's m16 tile x N=8 (samples 0-3 in cols 0-3) ----
        const uint32_t wbase = sbu + OFF_W + buf * W_BYTES;
        const uint32_t aaddr = wbase + (uint32_t)(wid * 16 + mrow) * 272u + (uint32_t)kof * 2u;
        const unsigned char* btp = sb + OFF_BT + buf * 2176 + g * 272 + tr * 4;

        float ca[4] = {0.f, 0.f, 0.f, 0.f}, cb[4] = {0.f, 0.f, 0.f, 0.f};
        #pragma unroll
        for (int kt = 0; kt < 4; ++kt) {
            uint32_t a0[4], a1[4];
            ldsm4(a0[0], a0[1], a0[2], a0[3], aaddr + kt * 32u);
            ldsm4(a1[0], a1[1], a1[2], a1[3], aaddr + (kt + 4) * 32u);
            const uint32_t b00 = *(const uint32_t*)(btp + kt * 32);
            const uint32_t b01 = *(const uint32_t*)(btp + kt * 32 + 16);
            const uint32_t b10 = *(const uint32_t*)(btp + (kt + 4) * 32);
            const uint32_t b11 = *(const uint32_t*)(btp + (kt + 4) * 32 + 16);
            mma16816(ca, a0, b00, b01);
            mma16816(cb, a1, b10, b11);
        }
        float cc[4];
        #pragma unroll
        for (int i = 0; i < 4; ++i) cc[i] = ca[i] + cb[i];

        // ---- epilogue: lane (g,tr) owns neurons n0=wid*16+g, n1=n0+8; cols 2tr,2tr+1 ----
        const int n0 = wid * 16 + g, n1 = n0 + 8;
        const int sA = (2 * tr) & 3, sBs = (2 * tr + 1) & 3;

        const int colprev = (r & 1) ? (col + 1) : (col - 1);
        const float xhA = (j == 0) ? 0.f : (float)((SB[sA * 32 + r] >> colprev) & 1u);
        const float xvA = (r == 0) ? 0.f : (float)((SB[sA * 32 + r - 1] >> col) & 1u);
        const float xhB = (j == 0) ? 0.f : (float)((SB[sBs * 32 + r] >> colprev) & 1u);
        const float xvB = (r == 0) ? 0.f : (float)((SB[sBs * 32 + r - 1] >> col) & 1u);
        const float eA = xhA + xvA, eB = xhB + xvB;

        const float4* AUX = (const float4*)(sb + OFF_AUX + buf * AUX_BYTES);
        const float4 x0 = AUX[n0], x1 = AUX[n1];

        const float h0A = tanh_fast(cc[0] + 2.f * x0.z + x0.x * eA + x0.y * (2.f - eA));
        const float h0B = tanh_fast(cc[1] + 2.f * x0.z + x0.x * eB + x0.y * (2.f - eB));
        const float h1A = tanh_fast(cc[2] + 2.f * x1.z + x1.x * eA + x1.y * (2.f - eA));
        const float h1B = tanh_fast(cc[3] + 2.f * x1.z + x1.x * eB + x1.y * (2.f - eB));

        // head partials: sum over g (lanes with same tr)
        float p0 = x0.w * h0A + x1.w * h1A;
        float p1 = x0.w * h0B + x1.w * h1B;
        #pragma unroll
        for (int o = 4; o <= 16; o <<= 1) {
            p0 += __shfl_xor_sync(0xffffffffu, p0, o);
            p1 += __shfl_xor_sync(0xffffffffu, p1, o);
        }
        if (lid < 2) RED[((c & 1) * 8 + wid) * 2 + lid] = make_float2(p0, p1);

        // hv + next-cell B build (tr0 -> samples 0,1 ; tr1 -> samples 2,3)
        if (tr < 2) {
            uint32_t* HVp = tr ? HV23 : HV01;
            const uint32_t pk0 = packbf2(h0A, h0B);
            const uint32_t pk1 = packbf2(h1A, h1B);
            HVp[col * 128 + n0] = pk0;
            HVp[col * 128 + n1] = pk1;
            if (c + 1 < NCELL) {
                const int cn = c + 1, rn = cn >> 5, jn = cn & 31;
                const int coln = (rn & 1) ? (LL - 1 - jn) : jn;
                float v0A = h0A, v0B = h0B, v1A = h1A, v1B = h1B;
                if (jn != 0) {
                    const uint32_t t0 = HVp[coln * 128 + n0];
                    const uint32_t t1 = HVp[coln * 128 + n1];
                    v0A += bflo(t0); v0B += bfhi(t0);
                    v1A += bflo(t1); v1B += bfhi(t1);
                }
                unsigned short* btA = (unsigned short*)(sb + OFF_BT + (buf ^ 1) * 2176) + sA * 136;
                unsigned short* btB = (unsigned short*)(sb + OFF_BT + (buf ^ 1) * 2176) + sBs * 136;
                btA[n0] = bf16b(v0A); btB[n0] = bf16b(v0B);
                btA[n1] = bf16b(v1A); btB[n1] = bf16b(v1B);
            }
        }
        __syncthreads();
    }

    // last cell's pre
    if (tid == 32) {
        const int pc = NCELL - 1, pr = pc >> 5, pj = pc & 31;
        const int pcol = (pr & 1) ? (LL - 1 - pj) : pj;
        float s01x = 0.f, s01y = 0.f, s23x = 0.f, s23y = 0.f;
        #pragma unroll
        for (int w = 0; w < 8; ++w) {
            const float2 qa = RED[((pc & 1) * 8 + w) * 2 + 0];
            const float2 qb = RED[((pc & 1) * 8 + w) * 2 + 1];
            s01x += qa.x; s01y += qa.y; s23x += qb.x; s23y += qb.y;
        }
        g_pre[blk][(pr << 5) + pcol] = make_float4(s01x, s01y, s23x, s23y);
    }
    __syncthreads();

    // ---- bulk log-prob (4 samples) ----
    float lp0 = 0.f, lp1 = 0.f, lp2 = 0.f, lp3 = 0.f;
    for (int c = tid; c < NCELL; c += NTHR) {
        const float bfv = __ldg(gBf + c);
        const float4 pr = g_pre[blk][c];
        const int row = c >> 5, bit = c & 31;
        float z, xh, m;
        z = pr.x + bfv; xh = 1.f / (1.f + __expf(-z));
        m = (float)((SB[row] >> bit) & 1u);
        lp0 += m * __logf(xh + EPSF) + (1.f - m) * __logf(1.f - xh + EPSF);
        z = pr.y + bfv; xh = 1.f / (1.f + __expf(-z));
        m = (float)((SB[32 + row] >> bit) & 1u);
        lp1 += m * __logf(xh + EPSF) + (1.f - m) * __logf(1.f - xh + EPSF);
        z = pr.z + bfv; xh = 1.f / (1.f + __expf(-z));
        m = (float)((SB[64 + row] >> bit) & 1u);
        lp2 += m * __logf(xh + EPSF) + (1.f - m) * __logf(1.f - xh + EPSF);
        z = pr.w + bfv; xh = 1.f / (1.f + __expf(-z));
        m = (float)((SB[96 + row] >> bit) & 1u);
        lp3 += m * __logf(xh + EPSF) + (1.f - m) * __logf(1.f - xh + EPSF);
    }
    #pragma unroll
    for (int o = 16; o; o >>= 1) {
        lp0 += __shfl_xor_sync(0xffffffffu, lp0, o);
        lp1 += __shfl_xor_sync(0xffffffffu, lp1, o);
        lp2 += __shfl_xor_sync(0xffffffffu, lp2, o);
        lp3 += __shfl_xor_sync(0xffffffffu, lp3, o);
    }
    float4* RED4 = (float4*)(sb + OFF_RED);
    if (lid == 0) RED4[wid] = make_float4(lp0, lp1, lp2, lp3);
    __syncthreads();
    if (tid < SPB) {
        float acc = 0.f;
        #pragma unroll
        for (int w = 0; w < 8; ++w) acc += ((const float*)&RED4[w])[tid];
        out[blk * SPB + tid] = acc;
    }
}

extern "C" void kernel_launch(void* const* d_in, const int* in_sizes, int n_in,
                              void* d_out, int out_size) {
    const float* samples = (const float*)d_in[0];
    const float* W1      = (const float*)d_in[1];
    const float* b1      = (const float*)d_in[2];
    const float* Wf      = (const float*)d_in[3];
    const float* bf      = (const float*)d_in[4];
    float* out = (float*)d_out;

    prep_kernel<<<NCELL, 256>>>(W1, b1, Wf);

    cudaFuncSetAttribute(rnn2d_kernel, cudaFuncAttributeMaxDynamicSharedMemorySize, (int)SMEM_SZ);
    rnn2d_kernel<<<NBLK, NTHR, SMEM_SZ>>>(samples, bf, out);
}